// round 12
// baseline (speedup 1.0000x reference)
#include <cuda_runtime.h>

#define N_NODES 10000
#define N_EDGES 160000
#define D1 128
#define D2 256
#define D3 512

#define GRID 148
#define TPB  1024
#define GT   (GRID * TPB)        // 151552
#define ROWSTRIDE (GT / 128)     // 1184 rows per sweep in phase P4
#define NROWS 9                  // max rows per thread (8*1184+528 = 10000)

// ---- persistent scratch (zero at load; re-zeroed at tail of every run) ----
// pair1[n] = (g1[n], s[n]) ; pair2[n] = (a2[n], t[n])
__device__ __align__(16) float2 g_p1[N_NODES];
__device__ __align__(16) float2 g_p2[N_NODES];
__device__ float g_a3[N_NODES];
__device__ float g_W12[D2];     // W1 @ W2   (plain stores each run)
__device__ float g_bW2[D2];     // b1 @ W2
// collapsed, PRE-HALVED weight vectors: [P/2 | Q/2 | R/2 | b3/2] (plain stores)
__device__ __align__(16) float g_PQRB[4 * D3];

// ---- grid barrier (count==0 between barriers; gen monotonic) ----
__device__ int g_bar_count;
__device__ volatile int g_bar_gen;

__device__ __forceinline__ void grid_bar() {
    __threadfence();
    __syncthreads();
    if (threadIdx.x == 0) {
        int gen = g_bar_gen;                 // snapshot BEFORE arriving
        if (atomicAdd(&g_bar_count, 1) == GRID - 1) {
            g_bar_count = 0;
            __threadfence();
            g_bar_gen = gen + 1;
        } else {
            while (g_bar_gen == gen) { __nanosleep(40); }
        }
    }
    __syncthreads();
}

__device__ __forceinline__ void red_add_v2(float2* addr, float a, float b) {
    asm volatile("red.global.add.v2.f32 [%0], {%1, %2};"
                 :: "l"(addr), "f"(a), "f"(b) : "memory");
}

__device__ __forceinline__ float fast_tanh(float h) {
    float r;
    asm("tanh.approx.f32 %0, %1;" : "=f"(r) : "f"(h));
    return r;
}

// ---- packed f32x2 helpers (ptxas emits FFMA2 only via PTX fma.rn.f32x2) ----
__device__ __forceinline__ unsigned long long pk2(float lo, float hi) {
    unsigned long long r;
    asm("mov.b64 %0, {%1, %2};" : "=l"(r) : "f"(lo), "f"(hi));
    return r;
}
__device__ __forceinline__ void upk2(float& lo, float& hi, unsigned long long v) {
    asm("mov.b64 {%0, %1}, %2;" : "=f"(lo), "=f"(hi) : "l"(v));
}
__device__ __forceinline__ unsigned long long fma2(unsigned long long a,
                                                   unsigned long long b,
                                                   unsigned long long c) {
    unsigned long long d;
    asm("fma.rn.f32x2 %0, %1, %2, %3;" : "=l"(d) : "l"(a), "l"(b), "l"(c));
    return d;
}

__global__ void __launch_bounds__(TPB, 1)
fused_gcn_kernel(const float* __restrict__ x,
                 const int*   __restrict__ ei,
                 const float* __restrict__ ew,
                 const float* __restrict__ W1,
                 const float* __restrict__ b1,
                 const float* __restrict__ W2,
                 const float* __restrict__ b2,
                 const float* __restrict__ W3,
                 const float* __restrict__ b3,
                 float* __restrict__ out) {
    __shared__ float s_red[1024];

    const int tid  = threadIdx.x;
    const int bid  = blockIdx.x;
    const int gtid = bid * TPB + tid;
    const int r0   = gtid >> 7;          // this thread's base output row

    // ---- cache this thread's 2 adjacent edges (vector loads) ----
    // 160000 = 2*80000: threads gtid<80000 own edges {2g, 2g+1}. 8B-aligned.
    const bool hasE = gtid < (N_EDGES / 2);
    int2 sv = make_int2(0, 0), dv = make_int2(0, 0);
    float2 wv = make_float2(0.f, 0.f);
    if (hasE) {
        sv = *reinterpret_cast<const int2*>(ei + 2 * gtid);
        dv = *reinterpret_cast<const int2*>(ei + N_EDGES + 2 * gtid);
        wv = *reinterpret_cast<const float2*>(ew + 2 * gtid);
    }

    // ===== P1: edge1 (all) || W12/bW2 GEMV (blocks 144-145) || b3/2 (146) ===
    // (g1,s)[dst] += (w*x[src], w)
    if (hasE) {
        red_add_v2(&g_p1[dv.x], wv.x * x[sv.x], wv.x);
        red_add_v2(&g_p1[dv.y], wv.y * x[sv.y], wv.y);
    }

    if (bid == 144 || bid == 145) {
        // one block per target vector: 256 cols x 4 j-chunks of 32
        const float* a = (bid == 144) ? W1 : b1;
        int k  = tid & 255;
        int jc = tid >> 8;              // 0..3
        int j0 = jc * 32;
        float acc = 0.f;
        #pragma unroll 8
        for (int jj = 0; jj < 32; jj++) {
            int j = j0 + jj;
            acc += a[j] * W2[j * D2 + k];
        }
        s_red[jc * 256 + k] = acc;
        __syncthreads();
        if (tid < 256) {
            float v = s_red[tid] + s_red[256 + tid] + s_red[512 + tid] + s_red[768 + tid];
            if (bid == 144) g_W12[tid] = v;
            else            g_bW2[tid] = v;
        }
    } else if (bid == 146) {
        if (tid < D3) g_PQRB[3 * D3 + tid] = 0.5f * b3[tid];
    }

    grid_bar();

    // ===== P2: edge2 (all) || P/Q/R GEMV (blocks 136-147) ===================
    // (a2,t)[dst] += w*(g1,s)[src]
    if (hasE) {
        float2 p = g_p1[sv.x];
        float2 q = g_p1[sv.y];
        red_add_v2(&g_p2[dv.x], wv.x * p.x, wv.x * p.y);
        red_add_v2(&g_p2[dv.y], wv.y * q.x, wv.y * q.y);
    }

    if (bid >= 136) {
        // 12 blocks: vec in {P,Q,R} x 4 col-quarters; 8 k-chunks of 32/thread
        int unit = bid - 136;           // 0..11
        int vec  = unit >> 2;           // 0..2
        int q    = unit & 3;
        int col  = q * 128 + (tid & 127);
        int c    = tid >> 7;            // 0..7
        const float* coef = (vec == 0) ? g_W12 : ((vec == 1) ? g_bW2 : b2);
        int j0 = c * 32;
        float acc = 0.f;
        #pragma unroll 8
        for (int jj = 0; jj < 32; jj++) {
            int j = j0 + jj;
            acc += coef[j] * W3[j * D3 + col];
        }
        s_red[c * 128 + (tid & 127)] = acc;
        __syncthreads();
        if (tid < 128) {
            float v = 0.f;
            #pragma unroll
            for (int c2 = 0; c2 < 8; c2++) v += s_red[c2 * 128 + tid];
            g_PQRB[vec * D3 + q * 128 + tid] = 0.5f * v;
        }
    }

    grid_bar();

    // ===== P3: edge3: a3[dst] += w*a2[src]  || preload (t,s) for P4 =========
    if (hasE) {
        atomicAdd(&g_a3[dv.x], wv.x * g_p2[sv.x].x);
        atomicAdd(&g_a3[dv.y], wv.y * g_p2[sv.y].x);
    }

    // (g1,s) and (a2,t) are FINAL after barrier 2: preload this thread's rows.
    // All p1/p2 reads thus complete before barrier 3 -> re-zeroable in P4
    // without extra synchronization.
    float tt[NROWS], ss[NROWS];
    #pragma unroll
    for (int k = 0; k < NROWS; k++) {
        int n = r0 + k * ROWSTRIDE;
        bool valid = (k < 8) || (n < N_NODES);
        tt[k] = valid ? g_p2[n].y : 0.f;
        ss[k] = valid ? g_p1[n].y : 0.f;
    }

    grid_bar();

    // ===== P4: out = 0.5*tanh(a3*P' + t*Q' + s*R' + B') + 0.5; re-zero ======
    {
        int j4 = (gtid & 127) << 2;     // loop-invariant feature offset
        float4 P = *reinterpret_cast<const float4*>(&g_PQRB[j4]);
        float4 Q = *reinterpret_cast<const float4*>(&g_PQRB[D3 + j4]);
        float4 R = *reinterpret_cast<const float4*>(&g_PQRB[2 * D3 + j4]);
        float4 B = *reinterpret_cast<const float4*>(&g_PQRB[3 * D3 + j4]);

        unsigned long long P01 = pk2(P.x, P.y), P23 = pk2(P.z, P.w);
        unsigned long long Q01 = pk2(Q.x, Q.y), Q23 = pk2(Q.z, Q.w);
        unsigned long long R01 = pk2(R.x, R.y), R23 = pk2(R.z, R.w);
        unsigned long long B01 = pk2(B.x, B.y), B23 = pk2(B.z, B.w);

        // batch the 9 (warp-uniform) a3 loads -> MLP 9
        float a3r[NROWS];
        #pragma unroll
        for (int k = 0; k < NROWS; k++) {
            int n = r0 + k * ROWSTRIDE;
            bool valid = (k < 8) || (n < N_NODES);
            a3r[k] = valid ? g_a3[n] : 0.f;
        }

        #pragma unroll
        for (int k = 0; k < NROWS; k++) {
            int n = r0 + k * ROWSTRIDE;
            bool valid = (k < 8) || (n < N_NODES);
            if (valid) {
                unsigned long long A2v = pk2(a3r[k], a3r[k]);
                unsigned long long T2  = pk2(tt[k], tt[k]);
                unsigned long long S2  = pk2(ss[k], ss[k]);

                unsigned long long u01 = fma2(A2v, P01, fma2(T2, Q01, fma2(S2, R01, B01)));
                unsigned long long u23 = fma2(A2v, P23, fma2(T2, Q23, fma2(S2, R23, B23)));

                float4 v;
                upk2(v.x, v.y, u01);
                upk2(v.z, v.w, u23);

                v.x = fmaf(0.5f, fast_tanh(v.x), 0.5f);
                v.y = fmaf(0.5f, fast_tanh(v.y), 0.5f);
                v.z = fmaf(0.5f, fast_tanh(v.z), 0.5f);
                v.w = fmaf(0.5f, fast_tanh(v.w), 0.5f);

                *reinterpret_cast<float4*>(&out[n * D3 + j4]) = v;

                // p1/p2 last read before barrier 3 -> safe to zero here
                if ((tid & 127) == 0) {
                    g_p1[n] = make_float2(0.f, 0.f);
                    g_p2[n] = make_float2(0.f, 0.f);
                }
            }
        }

        // a3 rows are read by 128 threads (4 warps) of this block above;
        // __syncthreads() orders those reads before the zeroing.
        __syncthreads();
        #pragma unroll
        for (int k = 0; k < NROWS; k++) {
            int n = r0 + k * ROWSTRIDE;
            bool valid = (k < 8) || (n < N_NODES);
            if (valid && (tid & 127) == 0) g_a3[n] = 0.f;
        }
    }
}

extern "C" void kernel_launch(void* const* d_in, const int* in_sizes, int n_in,
                              void* d_out, int out_size) {
    const float* x  = (const float*)d_in[0];
    const int*   ei = (const int*)d_in[1];
    const float* ew = (const float*)d_in[2];
    const float* W1 = (const float*)d_in[3];
    const float* b1 = (const float*)d_in[4];
    const float* W2 = (const float*)d_in[5];
    const float* b2 = (const float*)d_in[6];
    const float* W3 = (const float*)d_in[7];
    const float* b3 = (const float*)d_in[8];
    float* out = (float*)d_out;

    fused_gcn_kernel<<<GRID, TPB>>>(x, ei, ew, W1, b1, W2, b2, W3, b3, out);
}

// round 13
// speedup vs baseline: 1.0894x; 1.0894x over previous
#include <cuda_runtime.h>

#define N_NODES 10000
#define N_EDGES 160000
#define D1 128
#define D2 256
#define D3 512

#define GRID 148
#define TPB  1024
#define GT   (GRID * TPB)        // 151552
#define ROWSTRIDE (GT / 128)     // 1184 rows per sweep in phase P4

// ---- persistent scratch (zero at load; re-zeroed at tail of every run) ----
// pair1[n] = (g1[n], s[n]) ; pair2[n] = (a2[n], t[n])
__device__ __align__(16) float2 g_p1[N_NODES];
__device__ __align__(16) float2 g_p2[N_NODES];
__device__ float g_a3[N_NODES];
__device__ float g_W12[D2];     // W1 @ W2   (plain stores each run)
__device__ float g_bW2[D2];     // b1 @ W2
// collapsed, PRE-HALVED weight vectors: [P/2 | Q/2 | R/2 | b3/2] (plain stores)
__device__ __align__(16) float g_PQRB[4 * D3];

// ---- grid barrier (count==0 between barriers; gen monotonic) ----
__device__ int g_bar_count;
__device__ volatile int g_bar_gen;

__device__ __forceinline__ void grid_bar() {
    __threadfence();
    __syncthreads();
    if (threadIdx.x == 0) {
        int gen = g_bar_gen;                 // snapshot BEFORE arriving
        if (atomicAdd(&g_bar_count, 1) == GRID - 1) {
            g_bar_count = 0;
            __threadfence();
            g_bar_gen = gen + 1;
        } else {
            while (g_bar_gen == gen) { __nanosleep(40); }
        }
    }
    __syncthreads();
}

__device__ __forceinline__ void red_add_v2(float2* addr, float a, float b) {
    asm volatile("red.global.add.v2.f32 [%0], {%1, %2};"
                 :: "l"(addr), "f"(a), "f"(b) : "memory");
}

__device__ __forceinline__ float fast_tanh(float h) {
    float r;
    asm("tanh.approx.f32 %0, %1;" : "=f"(r) : "f"(h));
    return r;
}

// ---- packed f32x2 helpers (ptxas emits FFMA2 only via PTX fma.rn.f32x2) ----
__device__ __forceinline__ unsigned long long pk2(float lo, float hi) {
    unsigned long long r;
    asm("mov.b64 %0, {%1, %2};" : "=l"(r) : "f"(lo), "f"(hi));
    return r;
}
__device__ __forceinline__ void upk2(float& lo, float& hi, unsigned long long v) {
    asm("mov.b64 {%0, %1}, %2;" : "=f"(lo), "=f"(hi) : "l"(v));
}
__device__ __forceinline__ unsigned long long fma2(unsigned long long a,
                                                   unsigned long long b,
                                                   unsigned long long c) {
    unsigned long long d;
    asm("fma.rn.f32x2 %0, %1, %2, %3;" : "=l"(d) : "l"(a), "l"(b), "l"(c));
    return d;
}

__global__ void __launch_bounds__(TPB, 1)
fused_gcn_kernel(const float* __restrict__ x,
                 const int*   __restrict__ ei,
                 const float* __restrict__ ew,
                 const float* __restrict__ W1,
                 const float* __restrict__ b1,
                 const float* __restrict__ W2,
                 const float* __restrict__ b2,
                 const float* __restrict__ W3,
                 const float* __restrict__ b3,
                 float* __restrict__ out) {
    __shared__ float s_red[1024];

    const int tid  = threadIdx.x;
    const int bid  = blockIdx.x;
    const int gtid = bid * TPB + tid;

    // ---- cache this thread's 2 adjacent edges (vector loads, 8B-aligned) ---
    // 160000 = 2*80000: threads gtid<80000 own edges {2g, 2g+1}.
    const bool hasE = gtid < (N_EDGES / 2);
    int2 sv = make_int2(0, 0), dv = make_int2(0, 0);
    float2 wv = make_float2(0.f, 0.f);
    if (hasE) {
        sv = *reinterpret_cast<const int2*>(ei + 2 * gtid);
        dv = *reinterpret_cast<const int2*>(ei + N_EDGES + 2 * gtid);
        wv = *reinterpret_cast<const float2*>(ew + 2 * gtid);
    }

    // ===== P1: edge1 (all) || W12/bW2 GEMV (blocks 144-145) || b3/2 (146) ===
    // (g1,s)[dst] += (w*x[src], w)
    if (hasE) {
        red_add_v2(&g_p1[dv.x], wv.x * x[sv.x], wv.x);
        red_add_v2(&g_p1[dv.y], wv.y * x[sv.y], wv.y);
    }

    if (bid == 144 || bid == 145) {
        // one block per target vector: 256 cols x 4 j-chunks of 32
        const float* a = (bid == 144) ? W1 : b1;
        int k  = tid & 255;
        int jc = tid >> 8;              // 0..3
        int j0 = jc * 32;
        float acc = 0.f;
        #pragma unroll 8
        for (int jj = 0; jj < 32; jj++) {
            int j = j0 + jj;
            acc += a[j] * W2[j * D2 + k];
        }
        s_red[jc * 256 + k] = acc;
        __syncthreads();
        if (tid < 256) {
            float v = s_red[tid] + s_red[256 + tid] + s_red[512 + tid] + s_red[768 + tid];
            if (bid == 144) g_W12[tid] = v;
            else            g_bW2[tid] = v;
        }
    } else if (bid == 146) {
        if (tid < D3) g_PQRB[3 * D3 + tid] = 0.5f * b3[tid];
    }

    grid_bar();

    // ===== P2: edge2 (all) || P/Q/R GEMV (blocks 136-147) ===================
    // (a2,t)[dst] += w*(g1,s)[src]
    if (hasE) {
        float2 p = g_p1[sv.x];
        float2 q = g_p1[sv.y];
        red_add_v2(&g_p2[dv.x], wv.x * p.x, wv.x * p.y);
        red_add_v2(&g_p2[dv.y], wv.y * q.x, wv.y * q.y);
    }

    if (bid >= 136) {
        // 12 blocks: vec in {P,Q,R} x 4 col-quarters; 8 k-chunks of 32/thread
        int unit = bid - 136;           // 0..11
        int vec  = unit >> 2;           // 0..2
        int q    = unit & 3;
        int col  = q * 128 + (tid & 127);
        int c    = tid >> 7;            // 0..7
        const float* coef = (vec == 0) ? g_W12 : ((vec == 1) ? g_bW2 : b2);
        int j0 = c * 32;
        float acc = 0.f;
        #pragma unroll 8
        for (int jj = 0; jj < 32; jj++) {
            int j = j0 + jj;
            acc += coef[j] * W3[j * D3 + col];
        }
        s_red[c * 128 + (tid & 127)] = acc;
        __syncthreads();
        if (tid < 128) {
            float v = 0.f;
            #pragma unroll
            for (int c2 = 0; c2 < 8; c2++) v += s_red[c2 * 128 + tid];
            g_PQRB[vec * D3 + q * 128 + tid] = 0.5f * v;
        }
    }

    grid_bar();

    // ===== P3: edge3 (all): a3[dst] += w * a2[src] ==========================
    if (hasE) {
        atomicAdd(&g_a3[dv.x], wv.x * g_p2[sv.x].x);
        atomicAdd(&g_a3[dv.y], wv.y * g_p2[sv.y].x);
    }

    grid_bar();

    // ===== P4: out = 0.5*tanh(a3*P' + t*Q' + s*R' + B') + 0.5; then re-zero =
    {
        int j4 = (gtid & 127) << 2;     // loop-invariant feature offset
        float4 P = *reinterpret_cast<const float4*>(&g_PQRB[j4]);
        float4 Q = *reinterpret_cast<const float4*>(&g_PQRB[D3 + j4]);
        float4 R = *reinterpret_cast<const float4*>(&g_PQRB[2 * D3 + j4]);
        float4 B = *reinterpret_cast<const float4*>(&g_PQRB[3 * D3 + j4]);

        unsigned long long P01 = pk2(P.x, P.y), P23 = pk2(P.z, P.w);
        unsigned long long Q01 = pk2(Q.x, Q.y), Q23 = pk2(Q.z, Q.w);
        unsigned long long R01 = pk2(R.x, R.y), R23 = pk2(R.z, R.w);
        unsigned long long B01 = pk2(B.x, B.y), B23 = pk2(B.z, B.w);

        const int n0 = gtid >> 7;

        // depth-1 software pipeline: prefetch next row's 3 scalars while
        // computing the current row (hides the L2 broadcast latency)
        float a3 = g_a3[n0];
        float tt = g_p2[n0].y;
        float ss = g_p1[n0].y;

        for (int n = n0; n < N_NODES; n += ROWSTRIDE) {
            int np = n + ROWSTRIDE;
            float a3n = 0.f, ttn = 0.f, ssn = 0.f;
            if (np < N_NODES) {
                a3n = g_a3[np];
                ttn = g_p2[np].y;
                ssn = g_p1[np].y;
            }

            unsigned long long A2v = pk2(a3, a3);
            unsigned long long T2  = pk2(tt, tt);
            unsigned long long S2  = pk2(ss, ss);

            unsigned long long u01 = fma2(A2v, P01, fma2(T2, Q01, fma2(S2, R01, B01)));
            unsigned long long u23 = fma2(A2v, P23, fma2(T2, Q23, fma2(S2, R23, B23)));

            float4 v;
            upk2(v.x, v.y, u01);
            upk2(v.z, v.w, u23);

            v.x = fmaf(0.5f, fast_tanh(v.x), 0.5f);
            v.y = fmaf(0.5f, fast_tanh(v.y), 0.5f);
            v.z = fmaf(0.5f, fast_tanh(v.z), 0.5f);
            v.w = fmaf(0.5f, fast_tanh(v.w), 0.5f);

            *reinterpret_cast<float4*>(&out[n * D3 + j4]) = v;

            a3 = a3n; tt = ttn; ss = ssn;
        }

        // Tail re-zero: each block zeroes exactly the rows it just read.
        // Row n's 128 readers are 128 contiguous gtids, all inside this block
        // (128 | 1024), so __syncthreads() orders reads before zeroing.
        __syncthreads();
        for (int n = n0; n < N_NODES; n += ROWSTRIDE) {
            if ((tid & 127) == 0) {
                g_p1[n] = make_float2(0.f, 0.f);
                g_p2[n] = make_float2(0.f, 0.f);
                g_a3[n] = 0.f;
            }
        }
    }
}

extern "C" void kernel_launch(void* const* d_in, const int* in_sizes, int n_in,
                              void* d_out, int out_size) {
    const float* x  = (const float*)d_in[0];
    const int*   ei = (const int*)d_in[1];
    const float* ew = (const float*)d_in[2];
    const float* W1 = (const float*)d_in[3];
    const float* b1 = (const float*)d_in[4];
    const float* W2 = (const float*)d_in[5];
    const float* b2 = (const float*)d_in[6];
    const float* W3 = (const float*)d_in[7];
    const float* b3 = (const float*)d_in[8];
    float* out = (float*)d_out;

    fused_gcn_kernel<<<GRID, TPB>>>(x, ei, ew, W1, b1, W2, b2, W3, b3, out);
}